// round 6
// baseline (speedup 1.0000x reference)
#include <cuda_runtime.h>
#include <cuda_bf16.h>
#include <cstdint>

// Problem constants (shapes fixed by the dataset)
#define MAXN 100000
#define MAXE 1600000
#define FIN  128
#define FHID 64
#define FOUT 32

// ---------------- device scratch (no allocations allowed) ----------------
__device__ int   g_is64;          // 1 if edge_index is int64, 0 if int32
__device__ int   g_cnt[MAXN];     // in-degree (real edges only)
__device__ int   g_cur[MAXN];     // fill cursors
__device__ int   g_off[MAXN];     // CSR offsets (exclusive scan of cnt)
__device__ int   g_bsum[128];     // scan block sums
__device__ float g_dinv[MAXN];    // deg^{-1/2} (deg includes self loop)
__device__ int   g_src[MAXE];     // CSR: source node per (dst-sorted) edge
__device__ float g_g1[(size_t)MAXN * FHID];   // (x@W1)*dinv
__device__ float g_hact[(size_t)MAXN * FHID]; // relu layer-1 output
__device__ float g_g2[(size_t)MAXN * FOUT];   // (hact@W2)*dinv

// ---------------- small helpers ----------------
__device__ __forceinline__ unsigned long long pack_dup(float v) {
    unsigned long long r;
    asm("mov.b64 %0,{%1,%1};" : "=l"(r) : "f"(v));
    return r;
}
#define FMA2(acc, a, b) asm("fma.rn.f32x2 %0,%1,%2,%0;" : "+l"(acc) : "l"(a), "l"(b))

// Fetch edge endpoint #idx from the edge buffer under either dtype.
__device__ __forceinline__ int edge_at(const void* ei, long long idx, int is64) {
    if (is64) return (int)((const long long*)ei)[idx];
    return ((const int*)ei)[idx];
}

// ---------------- dtype detection ----------------
// int64 little-endian values < 2^31  => every odd 32-bit word is zero.
// int32 real indices                 => odd words are random node ids (nonzero).
__global__ void k_detect(const int* ei32) {
    if (threadIdx.x == 0) {
        int nz = 0;
        #pragma unroll 8
        for (int i = 0; i < 256; i++) nz |= ei32[2 * i + 1];
        g_is64 = (nz == 0) ? 1 : 0;
    }
}

// ---------------- CSR build ----------------
__global__ void k_zero(int n) {
    int i = blockIdx.x * blockDim.x + threadIdx.x;
    if (i < n) { g_cnt[i] = 0; g_cur[i] = 0; }
}

__global__ void k_count(const void* __restrict__ ei, int E, int n) {
    int e = blockIdx.x * blockDim.x + threadIdx.x;
    if (e < E) {
        int c = edge_at(ei, (long long)E + e, g_is64);   // col = dst
        if ((unsigned)c < (unsigned)n) atomicAdd(&g_cnt[c], 1);
    }
}

// Hillis-Steele per-block exclusive scan (1024 elems/block)
__global__ void k_scan1(int n) {
    __shared__ int s[1024];
    int tid = threadIdx.x;
    int i = blockIdx.x * 1024 + tid;
    int v = (i < n) ? g_cnt[i] : 0;
    s[tid] = v; __syncthreads();
    #pragma unroll
    for (int d = 1; d < 1024; d <<= 1) {
        int t = (tid >= d) ? s[tid - d] : 0;
        __syncthreads();
        s[tid] += t;
        __syncthreads();
    }
    if (i < n) g_off[i] = s[tid] - v;          // exclusive
    if (tid == 1023) g_bsum[blockIdx.x] = s[1023];
}

__global__ void k_scan2(int nb) {   // single block, nb <= 128
    __shared__ int s[128];
    int tid = threadIdx.x;
    int v = (tid < nb) ? g_bsum[tid] : 0;
    s[tid] = v; __syncthreads();
    #pragma unroll
    for (int d = 1; d < 128; d <<= 1) {
        int t = (tid >= d) ? s[tid - d] : 0;
        __syncthreads();
        s[tid] += t;
        __syncthreads();
    }
    if (tid < nb) g_bsum[tid] = s[tid] - v;    // exclusive block offsets
}

__global__ void k_scan3(int n) {
    int i = blockIdx.x * 1024 + threadIdx.x;
    if (i < n) g_off[i] += g_bsum[i >> 10];
}

__global__ void k_dinv(int n) {
    int i = blockIdx.x * blockDim.x + threadIdx.x;
    if (i < n) g_dinv[i] = rsqrtf((float)(g_cnt[i] + 1));  // +1 = self loop
}

__global__ void k_fill(const void* __restrict__ ei, int E, int n) {
    int e = blockIdx.x * blockDim.x + threadIdx.x;
    if (e < E) {
        int is64 = g_is64;
        int r = edge_at(ei, e, is64);                    // row = src
        int c = edge_at(ei, (long long)E + e, is64);     // col = dst
        if ((unsigned)c < (unsigned)n && (unsigned)r < (unsigned)n) {
            int p = g_off[c] + atomicAdd(&g_cur[c], 1);
            g_src[p] = r;
        }
    }
}

// ---------------- GEMM 1: g1 = (x @ W1) * dinv[row], f32x2 packed FMA ----------------
// block = 256 threads: 32 rows x 8 col-groups (8 cols each, 64 total)
// static smem: Ws 32KB + xs 16KB = 48KB; xs XOR-swizzled for conflict-free reads.
__global__ __launch_bounds__(256) void k_gemm1(const float* __restrict__ x,
                                               const float* __restrict__ W, int n) {
    __shared__ float Ws[FIN * FHID];     // [128][64] = 32KB
    __shared__ float xs[32 * FIN];       // [32][128] swizzled = 16KB
    int tid = threadIdx.x;
    int row0 = blockIdx.x * 32;

    for (int i = tid; i < FIN * FHID; i += 256) Ws[i] = W[i];
    for (int i = tid; i < 32 * FIN; i += 256) {
        int r = i >> 7, c = i & 127;
        int gr = row0 + r;
        xs[r * FIN + (c ^ ((r & 3) << 3))] = (gr < n) ? x[(size_t)gr * FIN + c] : 0.f;
    }
    __syncthreads();

    int r = tid >> 3;
    int c0 = (tid & 7) * 8;
    unsigned long long a0 = 0, a1 = 0, a2 = 0, a3 = 0;
    const float* xr = xs + r * FIN;
    int sw = (r & 3) << 3;
    #pragma unroll 16
    for (int k = 0; k < FIN; k++) {
        unsigned long long xp = pack_dup(xr[k ^ sw]);
        const ulonglong2* wp = (const ulonglong2*)(Ws + k * FHID + c0);
        ulonglong2 wa = wp[0], wb = wp[1];
        FMA2(a0, xp, wa.x);
        FMA2(a1, xp, wa.y);
        FMA2(a2, xp, wb.x);
        FMA2(a3, xp, wb.y);
    }
    int gr = row0 + r;
    if (gr < n) {
        float dv = g_dinv[gr];
        float o[8];
        asm("mov.b64 {%0,%1},%2;" : "=f"(o[0]), "=f"(o[1]) : "l"(a0));
        asm("mov.b64 {%0,%1},%2;" : "=f"(o[2]), "=f"(o[3]) : "l"(a1));
        asm("mov.b64 {%0,%1},%2;" : "=f"(o[4]), "=f"(o[5]) : "l"(a2));
        asm("mov.b64 {%0,%1},%2;" : "=f"(o[6]), "=f"(o[7]) : "l"(a3));
        float4* gp = (float4*)(g_g1 + (size_t)gr * FHID + c0);
        gp[0] = make_float4(o[0] * dv, o[1] * dv, o[2] * dv, o[3] * dv);
        gp[1] = make_float4(o[4] * dv, o[5] * dv, o[6] * dv, o[7] * dv);
    }
}

// ---------------- GEMM 2: g2 = (hact @ W2) * dinv[row] ----------------
// block = 256 threads: 64 rows x 4 col-groups (8 cols each, 32 total)
__global__ __launch_bounds__(256) void k_gemm2(const float* __restrict__ W, int n) {
    __shared__ float Ws[FHID * FOUT];            // 8KB
    __shared__ float xs[64][FHID + 1];           // ~16.6KB
    int tid = threadIdx.x;
    int row0 = blockIdx.x * 64;

    for (int i = tid; i < FHID * FOUT; i += 256) Ws[i] = W[i];
    for (int i = tid; i < 64 * FHID; i += 256) {
        int r = i >> 6, c = i & 63;
        int gr = row0 + r;
        xs[r][c] = (gr < n) ? g_hact[(size_t)gr * FHID + c] : 0.f;
    }
    __syncthreads();

    int r = tid >> 2;
    int c0 = (tid & 3) * 8;
    unsigned long long a0 = 0, a1 = 0, a2 = 0, a3 = 0;
    const float* xr = xs[r];
    #pragma unroll 16
    for (int k = 0; k < FHID; k++) {
        unsigned long long xp = pack_dup(xr[k]);
        const ulonglong2* wp = (const ulonglong2*)(Ws + k * FOUT + c0);
        ulonglong2 wa = wp[0], wb = wp[1];
        FMA2(a0, xp, wa.x);
        FMA2(a1, xp, wa.y);
        FMA2(a2, xp, wb.x);
        FMA2(a3, xp, wb.y);
    }
    int gr = row0 + r;
    if (gr < n) {
        float dv = g_dinv[gr];
        float o[8];
        asm("mov.b64 {%0,%1},%2;" : "=f"(o[0]), "=f"(o[1]) : "l"(a0));
        asm("mov.b64 {%0,%1},%2;" : "=f"(o[2]), "=f"(o[3]) : "l"(a1));
        asm("mov.b64 {%0,%1},%2;" : "=f"(o[4]), "=f"(o[5]) : "l"(a2));
        asm("mov.b64 {%0,%1},%2;" : "=f"(o[6]), "=f"(o[7]) : "l"(a3));
        float4* gp = (float4*)(g_g2 + (size_t)gr * FOUT + c0);
        gp[0] = make_float4(o[0] * dv, o[1] * dv, o[2] * dv, o[3] * dv);
        gp[1] = make_float4(o[4] * dv, o[5] * dv, o[6] * dv, o[7] * dv);
    }
}

// ---------------- Gather aggregation: one warp per node ----------------
// h_act[v] = relu( dinv[v] * (sum_{u->v} g1[u] + g1[v]) + b1 )
__global__ void k_gather1(const float* __restrict__ bias, int n) {
    int t = blockIdx.x * blockDim.x + threadIdx.x;
    int v = t >> 5;
    int lane = t & 31;
    if (v >= n) return;
    int base = g_off[v];
    int c = g_cnt[v];

    float2 acc = *(const float2*)(g_g1 + (size_t)v * FHID + lane * 2);  // self loop
    for (int j = 0; j < c; j++) {
        int u = __ldg(&g_src[base + j]);
        float2 tt = *(const float2*)(g_g1 + (size_t)u * FHID + lane * 2);
        acc.x += tt.x; acc.y += tt.y;
    }
    float dv = g_dinv[v];
    float o0 = fmaf(dv, acc.x, bias[lane * 2]);
    float o1 = fmaf(dv, acc.y, bias[lane * 2 + 1]);
    o0 = fmaxf(o0, 0.f); o1 = fmaxf(o1, 0.f);
    *(float2*)(g_hact + (size_t)v * FHID + lane * 2) = make_float2(o0, o1);
}

// out[v] = dinv[v] * (sum_{u->v} g2[u] + g2[v]) + b2
__global__ void k_gather2(const float* __restrict__ bias, float* __restrict__ outp, int n) {
    int t = blockIdx.x * blockDim.x + threadIdx.x;
    int v = t >> 5;
    int lane = t & 31;
    if (v >= n) return;
    int base = g_off[v];
    int c = g_cnt[v];

    float acc = g_g2[(size_t)v * FOUT + lane];  // self loop
    for (int j = 0; j < c; j++) {
        int u = __ldg(&g_src[base + j]);
        acc += g_g2[(size_t)u * FOUT + lane];
    }
    float dv = g_dinv[v];
    outp[(size_t)v * FOUT + lane] = fmaf(dv, acc, bias[lane]);
}

// ---------------- launch ----------------
extern "C" void kernel_launch(void* const* d_in, const int* in_sizes, int n_in,
                              void* d_out, int out_size) {
    const float* x   = (const float*)d_in[0];
    const void*  ei  = d_in[1];                 // int32 or int64, detected on device
    const float* W1  = (const float*)d_in[2];
    const float* b1  = (const float*)d_in[3];
    const float* W2  = (const float*)d_in[4];
    const float* b2  = (const float*)d_in[5];
    float*       out = (float*)d_out;

    int n = in_sizes[0] / FIN;     // 100000
    int E = in_sizes[1] / 2;       // 1600000 (element count is dtype-independent)

    int nb = (n + 1023) / 1024;

    k_detect<<<1, 32>>>((const int*)ei);
    k_zero  <<<(n + 255) / 256, 256>>>(n);
    k_count <<<(E + 255) / 256, 256>>>(ei, E, n);
    k_scan1 <<<nb, 1024>>>(n);
    k_scan2 <<<1, 128>>>(nb);
    k_scan3 <<<nb, 1024>>>(n);
    k_dinv  <<<(n + 255) / 256, 256>>>(n);
    k_fill  <<<(E + 255) / 256, 256>>>(ei, E, n);

    k_gemm1<<<(n + 31) / 32, 256>>>(x, W1, n);
    k_gather1<<<(int)(((size_t)n * 32 + 255) / 256), 256>>>(b1, n);
    k_gemm2<<<(n + 63) / 64, 256>>>(W2, n);
    k_gather2<<<(int)(((size_t)n * 32 + 255) / 256), 256>>>(b2, out, n);
}

// round 7
// speedup vs baseline: 2.0237x; 2.0237x over previous
#include <cuda_runtime.h>
#include <cuda_bf16.h>
#include <cstdint>

// Problem constants (shapes fixed by the dataset)
#define MAXN 100000
#define MAXE 1600000
#define FIN  128
#define FHID 64
#define FOUT 32

// GEMM tiling
#define G1_ROWS 128
#define G1_XSTR 132            // x-tile row stride (floats): mult of 4, bank-spread
#define G2_ROWS 256
#define G2_XSTR 68

// ---------------- device scratch (no allocations allowed) ----------------
__device__ int   g_is64;          // 1 if edge_index is int64, 0 if int32
__device__ int   g_cnt[MAXN];     // in-degree (real edges only)
__device__ int   g_cur[MAXN];     // fill cursors
__device__ int   g_off[MAXN];     // CSR offsets (exclusive scan of cnt)
__device__ int   g_bsum[128];     // scan block sums
__device__ float g_dinv[MAXN];    // deg^{-1/2} (deg includes self loop)
__device__ int   g_src[MAXE];     // CSR: source node per (dst-sorted) edge
__device__ float g_g1[(size_t)MAXN * FHID];   // (x@W1)*dinv
__device__ float g_hact[(size_t)MAXN * FHID]; // relu layer-1 output
__device__ float g_g2[(size_t)MAXN * FOUT];   // (hact@W2)*dinv

// ---------------- small helpers ----------------
__device__ __forceinline__ unsigned long long pack_dup(float v) {
    unsigned long long r;
    asm("mov.b64 %0,{%1,%1};" : "=l"(r) : "f"(v));
    return r;
}
#define FMA2(acc, a, b) asm("fma.rn.f32x2 %0,%1,%2,%0;" : "+l"(acc) : "l"(a), "l"(b))

__device__ __forceinline__ int edge_at(const void* ei, long long idx, int is64) {
    if (is64) return (int)((const long long*)ei)[idx];
    return ((const int*)ei)[idx];
}

// ---------------- init: zero counters + detect edge dtype ----------------
// int64 little-endian values < 2^31  => every odd 32-bit word is zero.
__global__ void k_init(const int* ei32, int n) {
    int i = blockIdx.x * blockDim.x + threadIdx.x;
    if (i < n) { g_cnt[i] = 0; g_cur[i] = 0; }
    if (blockIdx.x == 0 && threadIdx.x < 32) {
        int lane = threadIdx.x;
        int nz = 0;
        #pragma unroll
        for (int q = 0; q < 8; q++) nz |= ei32[2 * (lane * 8 + q) + 1];
        unsigned m = __ballot_sync(0xffffffffu, nz != 0);
        if (lane == 0) g_is64 = (m == 0) ? 1 : 0;
    }
}

__global__ void k_count(const void* __restrict__ ei, int E, int n) {
    int e = blockIdx.x * blockDim.x + threadIdx.x;
    if (e < E) {
        int c = edge_at(ei, (long long)E + e, g_is64);   // col = dst
        if ((unsigned)c < (unsigned)n) atomicAdd(&g_cnt[c], 1);
    }
}

__global__ void k_dinv(int n) {
    int i = blockIdx.x * blockDim.x + threadIdx.x;
    if (i < n) g_dinv[i] = rsqrtf((float)(g_cnt[i] + 1));  // +1 = self loop
}

// Hillis-Steele per-block exclusive scan (1024 elems/block)
__global__ void k_scan1(int n) {
    __shared__ int s[1024];
    int tid = threadIdx.x;
    int i = blockIdx.x * 1024 + tid;
    int v = (i < n) ? g_cnt[i] : 0;
    s[tid] = v; __syncthreads();
    #pragma unroll
    for (int d = 1; d < 1024; d <<= 1) {
        int t = (tid >= d) ? s[tid - d] : 0;
        __syncthreads();
        s[tid] += t;
        __syncthreads();
    }
    if (i < n) g_off[i] = s[tid] - v;          // exclusive
    if (tid == 1023) g_bsum[blockIdx.x] = s[1023];
}

__global__ void k_scan2(int nb) {   // single block, nb <= 128
    __shared__ int s[128];
    int tid = threadIdx.x;
    int v = (tid < nb) ? g_bsum[tid] : 0;
    s[tid] = v; __syncthreads();
    #pragma unroll
    for (int d = 1; d < 128; d <<= 1) {
        int t = (tid >= d) ? s[tid - d] : 0;
        __syncthreads();
        s[tid] += t;
        __syncthreads();
    }
    if (tid < nb) g_bsum[tid] = s[tid] - v;    // exclusive block offsets
}

__global__ void k_scan3(int n) {
    int i = blockIdx.x * 1024 + threadIdx.x;
    if (i < n) g_off[i] += g_bsum[i >> 10];
}

__global__ void k_fill(const void* __restrict__ ei, int E, int n) {
    int e = blockIdx.x * blockDim.x + threadIdx.x;
    if (e < E) {
        int is64 = g_is64;
        int r = edge_at(ei, e, is64);                    // row = src
        int c = edge_at(ei, (long long)E + e, is64);     // col = dst
        if ((unsigned)c < (unsigned)n && (unsigned)r < (unsigned)n) {
            int p = g_off[c] + atomicAdd(&g_cur[c], 1);
            g_src[p] = r;
        }
    }
}

// ---------------- GEMM 1: g1 = (x @ W1) * dinv[row] ----------------
// 256 threads = 8 colgroups x 32 rowgroups; thread: 4 rows x 8 cols.
// cols = {cg*4..+3, 32+cg*4..+3}  (W LDS.128 hits 32 distinct banks)
// rows = {rg + 32*i}              (x LDS.64 broadcast, banks rg*4 distinct)
__global__ __launch_bounds__(256) void k_gemm1(const float* __restrict__ x,
                                               const float* __restrict__ W, int n) {
    extern __shared__ float sm[];
    float* Ws = sm;                      // [128][64] = 32KB
    float* xs = sm + FIN * FHID;         // [128][132] = 67.6KB
    int tid = threadIdx.x;
    int row0 = blockIdx.x * G1_ROWS;

    for (int i = tid; i < FIN * FHID / 4; i += 256)
        ((float4*)Ws)[i] = ((const float4*)W)[i];
    for (int i = tid; i < G1_ROWS * (FIN / 4); i += 256) {
        int r = i >> 5, c4 = i & 31;
        int gr = row0 + r;
        float4 v = make_float4(0.f, 0.f, 0.f, 0.f);
        if (gr < n) v = ((const float4*)x)[(size_t)gr * (FIN / 4) + c4];
        *(float4*)(xs + r * G1_XSTR + c4 * 4) = v;
    }
    __syncthreads();

    int cg = tid & 7;
    int rg = tid >> 3;
    const float* xb = xs + rg * G1_XSTR;
    const float* w0 = Ws + cg * 4;
    const float* w1 = Ws + 32 + cg * 4;
    unsigned long long acc[4][4] = {};

    #pragma unroll 8
    for (int k = 0; k < FIN; k += 2) {
        ulonglong2 wA0 = *(const ulonglong2*)(w0 + k * FHID);
        ulonglong2 wB0 = *(const ulonglong2*)(w1 + k * FHID);
        ulonglong2 wA1 = *(const ulonglong2*)(w0 + (k + 1) * FHID);
        ulonglong2 wB1 = *(const ulonglong2*)(w1 + (k + 1) * FHID);
        #pragma unroll
        for (int i = 0; i < 4; i++) {
            float2 xv = *(const float2*)(xb + i * 32 * G1_XSTR + k);
            unsigned long long x0 = pack_dup(xv.x), x1 = pack_dup(xv.y);
            FMA2(acc[i][0], x0, wA0.x); FMA2(acc[i][1], x0, wA0.y);
            FMA2(acc[i][2], x0, wB0.x); FMA2(acc[i][3], x0, wB0.y);
            FMA2(acc[i][0], x1, wA1.x); FMA2(acc[i][1], x1, wA1.y);
            FMA2(acc[i][2], x1, wB1.x); FMA2(acc[i][3], x1, wB1.y);
        }
    }
    #pragma unroll
    for (int i = 0; i < 4; i++) {
        int gr = row0 + rg + 32 * i;
        if (gr < n) {
            float dv = g_dinv[gr];
            float o[8];
            asm("mov.b64 {%0,%1},%2;" : "=f"(o[0]), "=f"(o[1]) : "l"(acc[i][0]));
            asm("mov.b64 {%0,%1},%2;" : "=f"(o[2]), "=f"(o[3]) : "l"(acc[i][1]));
            asm("mov.b64 {%0,%1},%2;" : "=f"(o[4]), "=f"(o[5]) : "l"(acc[i][2]));
            asm("mov.b64 {%0,%1},%2;" : "=f"(o[6]), "=f"(o[7]) : "l"(acc[i][3]));
            float* gp = g_g1 + (size_t)gr * FHID;
            *(float4*)(gp + cg * 4)      = make_float4(o[0]*dv, o[1]*dv, o[2]*dv, o[3]*dv);
            *(float4*)(gp + 32 + cg * 4) = make_float4(o[4]*dv, o[5]*dv, o[6]*dv, o[7]*dv);
        }
    }
}

// ---------------- GEMM 2: g2 = (hact @ W2) * dinv[row] ----------------
// 256 threads = 4 colgroups x 64 rowgroups; thread: 4 rows x 8 cols.
// cols = {cg*4..+3, 16+cg*4..+3};  rows = {rg + 64*i}
__global__ __launch_bounds__(256) void k_gemm2(const float* __restrict__ W, int n) {
    extern __shared__ float sm[];
    float* Ws = sm;                      // [64][32] = 8KB
    float* xs = sm + FHID * FOUT;        // [256][68] = 69.6KB
    int tid = threadIdx.x;
    int row0 = blockIdx.x * G2_ROWS;

    for (int i = tid; i < FHID * FOUT / 4; i += 256)
        ((float4*)Ws)[i] = ((const float4*)W)[i];
    for (int i = tid; i < G2_ROWS * (FHID / 4); i += 256) {
        int r = i >> 4, c4 = i & 15;
        int gr = row0 + r;
        float4 v = make_float4(0.f, 0.f, 0.f, 0.f);
        if (gr < n) v = *(const float4*)(g_hact + (size_t)gr * FHID + c4 * 4);
        *(float4*)(xs + r * G2_XSTR + c4 * 4) = v;
    }
    __syncthreads();

    int cg = tid & 3;
    int rg = tid >> 2;
    const float* xb = xs + rg * G2_XSTR;
    const float* w0 = Ws + cg * 4;
    const float* w1 = Ws + 16 + cg * 4;
    unsigned long long acc[4][4] = {};

    #pragma unroll 8
    for (int k = 0; k < FHID; k += 2) {
        ulonglong2 wA0 = *(const ulonglong2*)(w0 + k * FOUT);
        ulonglong2 wB0 = *(const ulonglong2*)(w1 + k * FOUT);
        ulonglong2 wA1 = *(const ulonglong2*)(w0 + (k + 1) * FOUT);
        ulonglong2 wB1 = *(const ulonglong2*)(w1 + (k + 1) * FOUT);
        #pragma unroll
        for (int i = 0; i < 4; i++) {
            float2 xv = *(const float2*)(xb + i * 64 * G2_XSTR + k);
            unsigned long long x0 = pack_dup(xv.x), x1 = pack_dup(xv.y);
            FMA2(acc[i][0], x0, wA0.x); FMA2(acc[i][1], x0, wA0.y);
            FMA2(acc[i][2], x0, wB0.x); FMA2(acc[i][3], x0, wB0.y);
            FMA2(acc[i][0], x1, wA1.x); FMA2(acc[i][1], x1, wA1.y);
            FMA2(acc[i][2], x1, wB1.x); FMA2(acc[i][3], x1, wB1.y);
        }
    }
    #pragma unroll
    for (int i = 0; i < 4; i++) {
        int gr = row0 + rg + 64 * i;
        if (gr < n) {
            float dv = g_dinv[gr];
            float o[8];
            asm("mov.b64 {%0,%1},%2;" : "=f"(o[0]), "=f"(o[1]) : "l"(acc[i][0]));
            asm("mov.b64 {%0,%1},%2;" : "=f"(o[2]), "=f"(o[3]) : "l"(acc[i][1]));
            asm("mov.b64 {%0,%1},%2;" : "=f"(o[4]), "=f"(o[5]) : "l"(acc[i][2]));
            asm("mov.b64 {%0,%1},%2;" : "=f"(o[6]), "=f"(o[7]) : "l"(acc[i][3]));
            float* gp = g_g2 + (size_t)gr * FOUT;
            *(float4*)(gp + cg * 4)      = make_float4(o[0]*dv, o[1]*dv, o[2]*dv, o[3]*dv);
            *(float4*)(gp + 16 + cg * 4) = make_float4(o[4]*dv, o[5]*dv, o[6]*dv, o[7]*dv);
        }
    }
}

// ---------------- Gather aggregation: one warp per node, MLP=4 ----------------
// h_act[v] = relu( dinv[v] * (sum_{u->v} g1[u] + g1[v]) + b1 )
__global__ void k_gather1(const float* __restrict__ bias, int n) {
    int t = blockIdx.x * blockDim.x + threadIdx.x;
    int v = t >> 5;
    int lane = t & 31;
    if (v >= n) return;
    int base = g_off[v];
    int c = g_cnt[v];

    float2 acc = *(const float2*)(g_g1 + (size_t)v * FHID + lane * 2);  // self loop
    int j = 0;
    for (; j + 4 <= c; j += 4) {
        int u0 = __ldg(&g_src[base + j + 0]);
        int u1 = __ldg(&g_src[base + j + 1]);
        int u2 = __ldg(&g_src[base + j + 2]);
        int u3 = __ldg(&g_src[base + j + 3]);
        float2 t0 = __ldg((const float2*)(g_g1 + (size_t)u0 * FHID) + lane);
        float2 t1 = __ldg((const float2*)(g_g1 + (size_t)u1 * FHID) + lane);
        float2 t2 = __ldg((const float2*)(g_g1 + (size_t)u2 * FHID) + lane);
        float2 t3 = __ldg((const float2*)(g_g1 + (size_t)u3 * FHID) + lane);
        acc.x += t0.x + t1.x + t2.x + t3.x;
        acc.y += t0.y + t1.y + t2.y + t3.y;
    }
    for (; j < c; j++) {
        int u = __ldg(&g_src[base + j]);
        float2 tt = __ldg((const float2*)(g_g1 + (size_t)u * FHID) + lane);
        acc.x += tt.x; acc.y += tt.y;
    }
    float dv = g_dinv[v];
    float o0 = fmaf(dv, acc.x, bias[lane * 2]);
    float o1 = fmaf(dv, acc.y, bias[lane * 2 + 1]);
    o0 = fmaxf(o0, 0.f); o1 = fmaxf(o1, 0.f);
    *(float2*)(g_hact + (size_t)v * FHID + lane * 2) = make_float2(o0, o1);
}

// out[v] = dinv[v] * (sum_{u->v} g2[u] + g2[v]) + b2
__global__ void k_gather2(const float* __restrict__ bias, float* __restrict__ outp, int n) {
    int t = blockIdx.x * blockDim.x + threadIdx.x;
    int v = t >> 5;
    int lane = t & 31;
    if (v >= n) return;
    int base = g_off[v];
    int c = g_cnt[v];

    float acc = g_g2[(size_t)v * FOUT + lane];  // self loop
    int j = 0;
    for (; j + 4 <= c; j += 4) {
        int u0 = __ldg(&g_src[base + j + 0]);
        int u1 = __ldg(&g_src[base + j + 1]);
        int u2 = __ldg(&g_src[base + j + 2]);
        int u3 = __ldg(&g_src[base + j + 3]);
        float t0 = __ldg(g_g2 + (size_t)u0 * FOUT + lane);
        float t1 = __ldg(g_g2 + (size_t)u1 * FOUT + lane);
        float t2 = __ldg(g_g2 + (size_t)u2 * FOUT + lane);
        float t3 = __ldg(g_g2 + (size_t)u3 * FOUT + lane);
        acc += t0 + t1 + t2 + t3;
    }
    for (; j < c; j++) {
        int u = __ldg(&g_src[base + j]);
        acc += __ldg(g_g2 + (size_t)u * FOUT + lane);
    }
    float dv = g_dinv[v];
    outp[(size_t)v * FOUT + lane] = fmaf(dv, acc, bias[lane]);
}

// ---------------- launch ----------------
extern "C" void kernel_launch(void* const* d_in, const int* in_sizes, int n_in,
                              void* d_out, int out_size) {
    const float* x   = (const float*)d_in[0];
    const void*  ei  = d_in[1];                 // int32 or int64, detected on device
    const float* W1  = (const float*)d_in[2];
    const float* b1  = (const float*)d_in[3];
    const float* W2  = (const float*)d_in[4];
    const float* b2  = (const float*)d_in[5];
    float*       out = (float*)d_out;

    int n = in_sizes[0] / FIN;     // 100000
    int E = in_sizes[1] / 2;       // 1600000 (element count is dtype-independent)

    const int G1_SMEM = (FIN * FHID + G1_ROWS * G1_XSTR) * (int)sizeof(float);  // ~98KB
    const int G2_SMEM = (FHID * FOUT + G2_ROWS * G2_XSTR) * (int)sizeof(float); // ~76KB
    cudaFuncSetAttribute(k_gemm1, cudaFuncAttributeMaxDynamicSharedMemorySize, G1_SMEM);
    cudaFuncSetAttribute(k_gemm2, cudaFuncAttributeMaxDynamicSharedMemorySize, G2_SMEM);

    int nb = (n + 1023) / 1024;

    k_init <<<(n + 255) / 256, 256>>>((const int*)ei, n);
    k_count<<<(E + 255) / 256, 256>>>(ei, E, n);
    k_dinv <<<(n + 255) / 256, 256>>>(n);
    k_gemm1<<<(n + G1_ROWS - 1) / G1_ROWS, 256, G1_SMEM>>>(x, W1, n);   // launch #4: in ncu window
    k_scan1<<<nb, 1024>>>(n);
    k_scan2<<<1, 128>>>(nb);
    k_scan3<<<nb, 1024>>>(n);
    k_fill <<<(E + 255) / 256, 256>>>(ei, E, n);
    k_gather1<<<(int)(((size_t)n * 32 + 255) / 256), 256>>>(b1, n);
    k_gemm2<<<(n + G2_ROWS - 1) / G2_ROWS, 256, G2_SMEM>>>(W2, n);
    k_gather2<<<(int)(((size_t)n * 32 + 255) / 256), 256>>>(b2, out, n);
}

// round 9
// speedup vs baseline: 2.2357x; 1.1048x over previous
#include <cuda_runtime.h>
#include <cuda_bf16.h>
#include <cstdint>

// Problem constants (shapes fixed by the dataset)
#define MAXN 100000
#define MAXE 1600000
#define FIN  128
#define FHID 64
#define FOUT 32

// GEMM tiling
#define G1_ROWS 128
#define G2_ROWS 256

// ---------------- device scratch (no allocations allowed) ----------------
__device__ int   g_is64;          // 1 if edge_index is int64, 0 if int32
__device__ int   g_cnt[MAXN];     // in-degree (real edges only)
__device__ int   g_cur[MAXN];     // fill cursors
__device__ int   g_off[MAXN];     // CSR offsets (exclusive scan of cnt)
__device__ int   g_bsum[128];     // scan block sums
__device__ float g_dinv[MAXN];    // deg^{-1/2} (deg includes self loop)
__device__ int   g_src[MAXE];     // CSR: source node per (dst-sorted) edge
__device__ float g_g1[(size_t)MAXN * FHID];   // (x@W1)*dinv
__device__ float g_hact[(size_t)MAXN * FHID]; // relu layer-1 output
__device__ float g_g2[(size_t)MAXN * FOUT];   // (hact@W2)*dinv

// ---------------- small helpers ----------------
__device__ __forceinline__ unsigned long long pack_dup(float v) {
    unsigned long long r;
    asm("mov.b64 %0,{%1,%1};" : "=l"(r) : "f"(v));
    return r;
}
#define FMA2(acc, a, b) asm("fma.rn.f32x2 %0,%1,%2,%0;" : "+l"(acc) : "l"(a), "l"(b))

__device__ __forceinline__ int edge_at(const void* ei, long long idx, int is64) {
    if (is64) return (int)((const long long*)ei)[idx];
    return ((const int*)ei)[idx];
}

// ---------------- init: zero counters + detect edge dtype ----------------
// int64 little-endian values < 2^31  => every odd 32-bit word is zero.
__global__ void k_init(const int* ei32, int n) {
    int i = blockIdx.x * blockDim.x + threadIdx.x;
    if (i < n) { g_cnt[i] = 0; g_cur[i] = 0; }
    if (blockIdx.x == 0 && threadIdx.x < 32) {
        int lane = threadIdx.x;
        int nz = 0;
        #pragma unroll
        for (int q = 0; q < 8; q++) nz |= ei32[2 * (lane * 8 + q) + 1];
        unsigned m = __ballot_sync(0xffffffffu, nz != 0);
        if (lane == 0) g_is64 = (m == 0) ? 1 : 0;
    }
}

__global__ void k_count(const void* __restrict__ ei, int E, int n) {
    int e = blockIdx.x * blockDim.x + threadIdx.x;
    if (e < E) {
        int c = edge_at(ei, (long long)E + e, g_is64);   // col = dst
        if ((unsigned)c < (unsigned)n) atomicAdd(&g_cnt[c], 1);
    }
}

__global__ void k_dinv(int n) {
    int i = blockIdx.x * blockDim.x + threadIdx.x;
    if (i < n) g_dinv[i] = rsqrtf((float)(g_cnt[i] + 1));  // +1 = self loop
}

// Hillis-Steele per-block exclusive scan (1024 elems/block)
__global__ void k_scan1(int n) {
    __shared__ int s[1024];
    int tid = threadIdx.x;
    int i = blockIdx.x * 1024 + tid;
    int v = (i < n) ? g_cnt[i] : 0;
    s[tid] = v; __syncthreads();
    #pragma unroll
    for (int d = 1; d < 1024; d <<= 1) {
        int t = (tid >= d) ? s[tid - d] : 0;
        __syncthreads();
        s[tid] += t;
        __syncthreads();
    }
    if (i < n) g_off[i] = s[tid] - v;          // exclusive
    if (tid == 1023) g_bsum[blockIdx.x] = s[1023];
}

__global__ void k_scan2(int nb) {   // single block, nb <= 128
    __shared__ int s[128];
    int tid = threadIdx.x;
    int v = (tid < nb) ? g_bsum[tid] : 0;
    s[tid] = v; __syncthreads();
    #pragma unroll
    for (int d = 1; d < 128; d <<= 1) {
        int t = (tid >= d) ? s[tid - d] : 0;
        __syncthreads();
        s[tid] += t;
        __syncthreads();
    }
    if (tid < nb) g_bsum[tid] = s[tid] - v;    // exclusive block offsets
}

__global__ void k_scan3(int n) {
    int i = blockIdx.x * 1024 + threadIdx.x;
    if (i < n) g_off[i] += g_bsum[i >> 10];
}

__global__ void k_fill(const void* __restrict__ ei, int E, int n) {
    int e = blockIdx.x * blockDim.x + threadIdx.x;
    if (e < E) {
        int is64 = g_is64;
        int r = edge_at(ei, e, is64);                    // row = src
        int c = edge_at(ei, (long long)E + e, is64);     // col = dst
        if ((unsigned)c < (unsigned)n && (unsigned)r < (unsigned)n) {
            int p = g_off[c] + atomicAdd(&g_cur[c], 1);
            g_src[p] = r;
        }
    }
}

// ---------------- GEMM 1: g1 = (x @ W1) * dinv[row] ----------------
// 256 threads = 8 colgroups x 32 rowgroups; thread: 4 rows x 8 cols.
// W1 in smem (32KB); x read directly from global:
//   the 8 colgroup lanes of a warp share each x address -> 1 wavefront,
//   and the CTA's 64KB x tile stays L1-resident across the k loop.
__global__ __launch_bounds__(256) void k_gemm1(const float* __restrict__ x,
                                               const float* __restrict__ W, int n) {
    __shared__ float Ws[FIN * FHID];     // [128][64] = 32KB
    int tid = threadIdx.x;
    int row0 = blockIdx.x * G1_ROWS;

    for (int i = tid; i < FIN * FHID / 4; i += 256)
        ((float4*)Ws)[i] = ((const float4*)W)[i];
    __syncthreads();

    int cg = tid & 7;
    int rg = tid >> 3;
    int r0 = row0 + rg, r1 = r0 + 32, r2 = r0 + 64, r3 = r0 + 96;
    const float* xr0 = x + (size_t)min(r0, n - 1) * FIN;
    const float* xr1 = x + (size_t)min(r1, n - 1) * FIN;
    const float* xr2 = x + (size_t)min(r2, n - 1) * FIN;
    const float* xr3 = x + (size_t)min(r3, n - 1) * FIN;
    const float* w0 = Ws + cg * 4;
    const float* w1 = Ws + 32 + cg * 4;
    unsigned long long acc[4][4] = {};

    #pragma unroll 4
    for (int k = 0; k < FIN; k += 4) {
        float4 xv0 = __ldg((const float4*)(xr0 + k));
        float4 xv1 = __ldg((const float4*)(xr1 + k));
        float4 xv2 = __ldg((const float4*)(xr2 + k));
        float4 xv3 = __ldg((const float4*)(xr3 + k));
        #pragma unroll
        for (int s = 0; s < 4; s++) {
            ulonglong2 wA = *(const ulonglong2*)(w0 + (k + s) * FHID);
            ulonglong2 wB = *(const ulonglong2*)(w1 + (k + s) * FHID);
            unsigned long long d0 = pack_dup(((const float*)&xv0)[s]);
            unsigned long long d1 = pack_dup(((const float*)&xv1)[s]);
            unsigned long long d2 = pack_dup(((const float*)&xv2)[s]);
            unsigned long long d3 = pack_dup(((const float*)&xv3)[s]);
            FMA2(acc[0][0], d0, wA.x); FMA2(acc[0][1], d0, wA.y);
            FMA2(acc[0][2], d0, wB.x); FMA2(acc[0][3], d0, wB.y);
            FMA2(acc[1][0], d1, wA.x); FMA2(acc[1][1], d1, wA.y);
            FMA2(acc[1][2], d1, wB.x); FMA2(acc[1][3], d1, wB.y);
            FMA2(acc[2][0], d2, wA.x); FMA2(acc[2][1], d2, wA.y);
            FMA2(acc[2][2], d2, wB.x); FMA2(acc[2][3], d2, wB.y);
            FMA2(acc[3][0], d3, wA.x); FMA2(acc[3][1], d3, wA.y);
            FMA2(acc[3][2], d3, wB.x); FMA2(acc[3][3], d3, wB.y);
        }
    }
    #pragma unroll
    for (int i = 0; i < 4; i++) {
        int gr = row0 + rg + 32 * i;
        if (gr < n) {
            float dv = g_dinv[gr];
            float o[8];
            asm("mov.b64 {%0,%1},%2;" : "=f"(o[0]), "=f"(o[1]) : "l"(acc[i][0]));
            asm("mov.b64 {%0,%1},%2;" : "=f"(o[2]), "=f"(o[3]) : "l"(acc[i][1]));
            asm("mov.b64 {%0,%1},%2;" : "=f"(o[4]), "=f"(o[5]) : "l"(acc[i][2]));
            asm("mov.b64 {%0,%1},%2;" : "=f"(o[6]), "=f"(o[7]) : "l"(acc[i][3]));
            float* gp = g_g1 + (size_t)gr * FHID;
            *(float4*)(gp + cg * 4)      = make_float4(o[0]*dv, o[1]*dv, o[2]*dv, o[3]*dv);
            *(float4*)(gp + 32 + cg * 4) = make_float4(o[4]*dv, o[5]*dv, o[6]*dv, o[7]*dv);
        }
    }
}

// ---------------- GEMM 2: g2 = (hact @ W2) * dinv[row] ----------------
// 256 threads = 4 colgroups x 64 rowgroups; thread: 4 rows x 8 cols.
__global__ __launch_bounds__(256) void k_gemm2(const float* __restrict__ W, int n) {
    __shared__ float Ws[FHID * FOUT];    // [64][32] = 8KB
    int tid = threadIdx.x;
    int row0 = blockIdx.x * G2_ROWS;

    for (int i = tid; i < FHID * FOUT / 4; i += 256)
        ((float4*)Ws)[i] = ((const float4*)W)[i];
    __syncthreads();

    int cg = tid & 3;
    int rg = tid >> 2;
    int r0 = row0 + rg, r1 = r0 + 64, r2 = r0 + 128, r3 = r0 + 192;
    const float* xr0 = g_hact + (size_t)min(r0, n - 1) * FHID;
    const float* xr1 = g_hact + (size_t)min(r1, n - 1) * FHID;
    const float* xr2 = g_hact + (size_t)min(r2, n - 1) * FHID;
    const float* xr3 = g_hact + (size_t)min(r3, n - 1) * FHID;
    const float* w0 = Ws + cg * 4;
    const float* w1 = Ws + 16 + cg * 4;
    unsigned long long acc[4][4] = {};

    #pragma unroll 4
    for (int k = 0; k < FHID; k += 4) {
        float4 xv0 = __ldg((const float4*)(xr0 + k));
        float4 xv1 = __ldg((const float4*)(xr1 + k));
        float4 xv2 = __ldg((const float4*)(xr2 + k));
        float4 xv3 = __ldg((const float4*)(xr3 + k));
        #pragma unroll
        for (int s = 0; s < 4; s++) {
            ulonglong2 wA = *(const ulonglong2*)(w0 + (k + s) * FOUT);
            ulonglong2 wB = *(const ulonglong2*)(w1 + (k + s) * FOUT);
            unsigned long long d0 = pack_dup(((const float*)&xv0)[s]);
            unsigned long long d1 = pack_dup(((const float*)&xv1)[s]);
            unsigned long long d2 = pack_dup(((const float*)&xv2)[s]);
            unsigned long long d3 = pack_dup(((const float*)&xv3)[s]);
            FMA2(acc[0][0], d0, wA.x); FMA2(acc[0][1], d0, wA.y);
            FMA2(acc[0][2], d0, wB.x); FMA2(acc[0][3], d0, wB.y);
            FMA2(acc[1][0], d1, wA.x); FMA2(acc[1][1], d1, wA.y);
            FMA2(acc[1][2], d1, wB.x); FMA2(acc[1][3], d1, wB.y);
            FMA2(acc[2][0], d2, wA.x); FMA2(acc[2][1], d2, wA.y);
            FMA2(acc[2][2], d2, wB.x); FMA2(acc[2][3], d2, wB.y);
            FMA2(acc[3][0], d3, wA.x); FMA2(acc[3][1], d3, wA.y);
            FMA2(acc[3][2], d3, wB.x); FMA2(acc[3][3], d3, wB.y);
        }
    }
    #pragma unroll
    for (int i = 0; i < 4; i++) {
        int gr = row0 + rg + 64 * i;
        if (gr < n) {
            float dv = g_dinv[gr];
            float o[8];
            asm("mov.b64 {%0,%1},%2;" : "=f"(o[0]), "=f"(o[1]) : "l"(acc[i][0]));
            asm("mov.b64 {%0,%1},%2;" : "=f"(o[2]), "=f"(o[3]) : "l"(acc[i][1]));
            asm("mov.b64 {%0,%1},%2;" : "=f"(o[4]), "=f"(o[5]) : "l"(acc[i][2]));
            asm("mov.b64 {%0,%1},%2;" : "=f"(o[6]), "=f"(o[7]) : "l"(acc[i][3]));
            float* gp = g_g2 + (size_t)gr * FOUT;
            *(float4*)(gp + cg * 4)      = make_float4(o[0]*dv, o[1]*dv, o[2]*dv, o[3]*dv);
            *(float4*)(gp + 16 + cg * 4) = make_float4(o[4]*dv, o[5]*dv, o[6]*dv, o[7]*dv);
        }
    }
}

// ---------------- Gather aggregation: one warp per node, MLP=4 ----------------
// h_act[v] = relu( dinv[v] * (sum_{u->v} g1[u] + g1[v]) + b1 )
__global__ void k_gather1(const float* __restrict__ bias, int n) {
    int t = blockIdx.x * blockDim.x + threadIdx.x;
    int v = t >> 5;
    int lane = t & 31;
    if (v >= n) return;
    int base = g_off[v];
    int c = g_cnt[v];

    float2 acc = *(const float2*)(g_g1 + (size_t)v * FHID + lane * 2);  // self loop
    int j = 0;
    for (; j + 4 <= c; j += 4) {
        int u0 = __ldg(&g_src[base + j + 0]);
        int u1 = __ldg(&g_src[base + j + 1]);
        int u2 = __ldg(&g_src[base + j + 2]);
        int u3 = __ldg(&g_src[base + j + 3]);
        float2 t0 = __ldg((const float2*)(g_g1 + (size_t)u0 * FHID) + lane);
        float2 t1 = __ldg((const float2*)(g_g1 + (size_t)u1 * FHID) + lane);
        float2 t2 = __ldg((const float2*)(g_g1 + (size_t)u2 * FHID) + lane);
        float2 t3 = __ldg((const float2*)(g_g1 + (size_t)u3 * FHID) + lane);
        acc.x += t0.x + t1.x + t2.x + t3.x;
        acc.y += t0.y + t1.y + t2.y + t3.y;
    }
    for (; j < c; j++) {
        int u = __ldg(&g_src[base + j]);
        float2 tt = __ldg((const float2*)(g_g1 + (size_t)u * FHID) + lane);
        acc.x += tt.x; acc.y += tt.y;
    }
    float dv = g_dinv[v];
    float o0 = fmaf(dv, acc.x, bias[lane * 2]);
    float o1 = fmaf(dv, acc.y, bias[lane * 2 + 1]);
    o0 = fmaxf(o0, 0.f); o1 = fmaxf(o1, 0.f);
    *(float2*)(g_hact + (size_t)v * FHID + lane * 2) = make_float2(o0, o1);
}

// out[v] = dinv[v] * (sum_{u->v} g2[u] + g2[v]) + b2
__global__ void k_gather2(const float* __restrict__ bias, float* __restrict__ outp, int n) {
    int t = blockIdx.x * blockDim.x + threadIdx.x;
    int v = t >> 5;
    int lane = t & 31;
    if (v >= n) return;
    int base = g_off[v];
    int c = g_cnt[v];

    float acc = g_g2[(size_t)v * FOUT + lane];  // self loop
    int j = 0;
    for (; j + 4 <= c; j += 4) {
        int u0 = __ldg(&g_src[base + j + 0]);
        int u1 = __ldg(&g_src[base + j + 1]);
        int u2 = __ldg(&g_src[base + j + 2]);
        int u3 = __ldg(&g_src[base + j + 3]);
        float t0 = __ldg(g_g2 + (size_t)u0 * FOUT + lane);
        float t1 = __ldg(g_g2 + (size_t)u1 * FOUT + lane);
        float t2 = __ldg(g_g2 + (size_t)u2 * FOUT + lane);
        float t3 = __ldg(g_g2 + (size_t)u3 * FOUT + lane);
        acc += t0 + t1 + t2 + t3;
    }
    for (; j < c; j++) {
        int u = __ldg(&g_src[base + j]);
        acc += __ldg(g_g2 + (size_t)u * FOUT + lane);
    }
    float dv = g_dinv[v];
    outp[(size_t)v * FOUT + lane] = fmaf(dv, acc, bias[lane]);
}

// ---------------- launch ----------------
extern "C" void kernel_launch(void* const* d_in, const int* in_sizes, int n_in,
                              void* d_out, int out_size) {
    const float* x   = (const float*)d_in[0];
    const void*  ei  = d_in[1];                 // int32 or int64, detected on device
    const float* W1  = (const float*)d_in[2];
    const float* b1  = (const float*)d_in[3];
    const float* W2  = (const float*)d_in[4];
    const float* b2  = (const float*)d_in[5];
    float*       out = (float*)d_out;

    int n = in_sizes[0] / FIN;     // 100000
    int E = in_sizes[1] / 2;       // 1600000 (element count is dtype-independent)

    int nb = (n + 1023) / 1024;

    k_init <<<(n + 255) / 256, 256>>>((const int*)ei, n);
    k_count<<<(E + 255) / 256, 256>>>(ei, E, n);
    k_dinv <<<(n + 255) / 256, 256>>>(n);
    k_gemm1<<<(n + G1_ROWS - 1) / G1_ROWS, 256>>>(x, W1, n);   // launch #4: in ncu window
    k_scan1<<<nb, 1024>>>(n);
    k_scan2<<<1, 128>>>(nb);
    k_scan3<<<nb, 1024>>>(n);
    k_fill <<<(E + 255) / 256, 256>>>(ei, E, n);
    k_gather1<<<(int)(((size_t)n * 32 + 255) / 256), 256>>>(b1, n);
    k_gemm2<<<(n + G2_ROWS - 1) / G2_ROWS, 256>>>(W2, n);
    k_gather2<<<(int)(((size_t)n * 32 + 255) / 256), 256>>>(b2, out, n);
}